// round 13
// baseline (speedup 1.0000x reference)
#include <cuda_runtime.h>
#include <cstdint>

// ConvAttentionModule — one kernel, 8-CTA cluster, DISTRIBUTED-PUSH exchange.
//   s[n]   = tanh( (1/32) * Sum_{8 batches, 2x2 patch} x ),  n in [0,4096)
//   ctx[n] = g(t)/h(t), t = 8 s[n], h(t) = Sum_m exp(t s_m), g = h'
//            via degree-15 Taylor in moments M_k = Sum_m s_m^k  (gate 1e-3)
//   out[b] = (mean_n ctx[n]) * Sum_d w[d] + b0              (same for all b)
//
// Comm design (lessons R8/R9/R11):
//  - ONE cluster barrier, issued while the 16 x-loads are in flight (its
//    ~490cyc hides under DRAM/L2 latency; also publishes mbarrier inits).
//  - Moment exchange: 128 threads each make ONE remote store (data travels
//    first), __syncthreads, then 8 threads each make ONE release-arrive to a
//    distinct peer (cumulativity covers the other threads' stores).
//    Receiver: local acquire-wait, then LOCAL smem reads — no pull RTT.
//  - Final: per-CTA partial pushed to CTA0 + 8-count mbarrier; peers exit.
// No global scratch, no atomics -> replay-deterministic.

#define KM  16           // moments M_1..M_16 (series degree 15) = 16 warps
#define NC  8            // cluster size = grid size
#define NLD 585          // 9 rows x 65 cols per CTA

__constant__ float c_invk[KM] = {
    0.f,    1.f,    1.f/2,  1.f/3,  1.f/4,  1.f/5,  1.f/6,  1.f/7,
    1.f/8,  1.f/9,  1.f/10, 1.f/11, 1.f/12, 1.f/13, 1.f/14, 1.f/15
};

__device__ __forceinline__ float warp_sum(float v) {
    v += __shfl_xor_sync(0xffffffffu, v, 16);
    v += __shfl_xor_sync(0xffffffffu, v, 8);
    v += __shfl_xor_sync(0xffffffffu, v, 4);
    v += __shfl_xor_sync(0xffffffffu, v, 2);
    v += __shfl_xor_sync(0xffffffffu, v, 1);
    return v;
}

__device__ __forceinline__ uint32_t smem_u32(const void* p) {
    return (uint32_t)__cvta_generic_to_shared(p);
}
__device__ __forceinline__ void dsmem_st(float* p, uint32_t rank, float v) {
    uint32_t a = smem_u32(p), ra;
    asm volatile("mapa.shared::cluster.u32 %0, %1, %2;" : "=r"(ra) : "r"(a), "r"(rank));
    asm volatile("st.shared::cluster.f32 [%0], %1;" :: "r"(ra), "f"(v) : "memory");
}
// release-arrive (cluster scope) on `rank`'s copy of this mbarrier
__device__ __forceinline__ void mbar_arrive_rank(void* mbar, uint32_t rank) {
    uint32_t a = smem_u32(mbar), ra;
    asm volatile("mapa.shared::cluster.u32 %0, %1, %2;" : "=r"(ra) : "r"(a), "r"(rank));
    asm volatile("mbarrier.arrive.release.cluster.shared::cluster.b64 _, [%0];"
                 :: "r"(ra) : "memory");
}
// acquire-wait (cluster scope) on the LOCAL mbarrier, phase parity 0
__device__ __forceinline__ void mbar_wait0(void* mbar) {
    uint32_t a = smem_u32(mbar);
    asm volatile(
        "{\n\t"
        ".reg .pred P;\n\t"
        "WAIT_%=:\n\t"
        "mbarrier.try_wait.parity.acquire.cluster.shared::cta.b64 P, [%0], 0, 0x989680;\n\t"
        "@P bra.uni DONE_%=;\n\t"
        "bra.uni WAIT_%=;\n\t"
        "DONE_%=:\n\t"
        "}" :: "r"(a) : "memory");
}
#define CLUSTER_SYNC() do { \
    asm volatile("barrier.cluster.arrive.aligned;" ::: "memory"); \
    asm volatile("barrier.cluster.wait.aligned;"   ::: "memory"); \
} while (0)

__global__ void __launch_bounds__(512, 1) __cluster_dims__(NC, 1, 1)
k_fused(const float* __restrict__ x, const float* __restrict__ w,
        const float* __restrict__ pb, float* __restrict__ out) {
    __shared__ float y[9 * 66];           // this CTA's 9 batch-summed rows
    __shared__ float spow[KM][512];       // s^{k+1} per thread (32 KB)
    __shared__ float Mpart[KM];           // this CTA's moment partials
    __shared__ float Mrecv[NC][KM];       // partials pushed in by every CTA
    __shared__ float Ms[KM + 1];          // finalized moments, Ms[0] = 4096
    __shared__ float red[16];             // per-warp ctx partials
    __shared__ float cpart[NC];           // per-CTA ctx partials (CTA0 target)
    __shared__ alignas(8) unsigned long long mbarM;  // 8 arrivals (one per src CTA)
    __shared__ alignas(8) unsigned long long mbarC;  // 8 arrivals (CTA0 only)

    const int tid  = threadIdx.x;         // 512
    const int bid  = blockIdx.x;          // 8
    const int wid  = tid >> 5;            // 16 warps
    const int lane = tid & 31;

    // Prefetch final-stage operands (CTA0 warp0) + init mbarriers
    float w_pre = 0.f, b_pre = 0.f;
    if (bid == 0 && tid < 32) {
        w_pre = w[lane] + w[lane + 32];
        b_pre = pb[0];
    }
    if (tid == 0) {
        uint32_t aM = smem_u32(&mbarM), aC = smem_u32(&mbarC);
        asm volatile("mbarrier.init.shared.b64 [%0], %1;" :: "r"(aM), "r"(NC) : "memory");
        asm volatile("mbarrier.init.shared.b64 [%0], %1;" :: "r"(aC), "r"(NC) : "memory");
    }

    // ---- Issue all x loads FIRST (stay in flight across the barrier) ----
    const float* xb = x + 520 * bid;      // rows 8*bid .. 8*bid+8
    const int i0 = tid, i1 = tid + 512;
    const bool v1 = (i1 < NLD);
    float r0[8], r1[8];
#pragma unroll
    for (int b = 0; b < 8; ++b) r0[b] = xb[b * 4225 + i0];
#pragma unroll
    for (int b = 0; b < 8; ++b) r1[b] = v1 ? xb[b * 4225 + i1] : 0.f;

    // ---- Cluster sync: publishes mbarrier inits; hidden under load wait ----
    CLUSTER_SYNC();

    // ---- Phase A: consume loads, batch-summed rows into smem ----
    {
        float a0 = (r0[0] + r0[1]) + (r0[2] + r0[3])
                 + (r0[4] + r0[5]) + (r0[6] + r0[7]);
        int r = i0 / 65, c = i0 - r * 65;
        y[r * 66 + c] = a0;
        if (v1) {
            float a1 = (r1[0] + r1[1]) + (r1[2] + r1[3])
                     + (r1[4] + r1[5]) + (r1[6] + r1[7]);
            int r2 = i1 / 65, c2 = i1 - r2 * 65;
            y[r2 * 66 + c2] = a1;
        }
    }
    __syncthreads();

    // ---- Phase B: patch scalar + power table ----
    const int il = tid >> 6, j = tid & 63;
    const float* p = &y[il * 66 + j];
    const float s = tanhf((p[0] + p[1] + p[66] + p[67]) * 0.03125f);
    {
        float pw = s;
        spow[0][tid] = pw;
#pragma unroll
        for (int k = 1; k < KM; ++k) { pw *= s; spow[k][tid] = pw; }
    }
    __syncthreads();

    // ---- Phase C: warp w sums order w+1 (coalesced LDS, one warp_sum) ----
    {
        float a = 0.f;
#pragma unroll
        for (int i = 0; i < 16; ++i) a += spow[wid][i * 32 + lane];
        a = warp_sum(a);
        if (lane == 0) Mpart[wid] = a;
    }
    __syncthreads();

    // ---- Distributed PUSH: one remote store per thread (tid<128),
    //      then one release-arrive per peer (tid<8). ----
    if (tid < NC * KM) {                  // tid -> (dest rank, order)
        int r = tid >> 4, k = tid & 15;
        dsmem_st(&Mrecv[bid][k], (uint32_t)r, Mpart[k]);
    }
    __syncthreads();                      // stores happen-before the arrives
    if (tid < NC) mbar_arrive_rank(&mbarM, (uint32_t)tid);

    // ---- Wait (local acquire) then LOCAL finalize of moments ----
    if (tid == 0) mbar_wait0(&mbarM);
    __syncthreads();
    if (tid < KM) {
        float m = 0.f;
#pragma unroll
        for (int r = 0; r < NC; ++r) m += Mrecv[r][tid];
        Ms[tid + 1] = m;
    }
    if (tid == KM) Ms[0] = 4096.f;
    __syncthreads();

    // ---- Phase D: degree-15 series + block reduction ----
    const float t = 8.f * s;
    float term = 1.f;
    float hh = Ms[0];
    float gg = Ms[1];
#pragma unroll
    for (int k = 1; k <= KM - 1; ++k) {
        term *= t * c_invk[k];            // t^k / k!
        hh += Ms[k]     * term;
        gg += Ms[k + 1] * term;
    }
    float v = warp_sum(__fdividef(gg, hh));
    if (lane == 0) red[wid] = v;
    __syncthreads();

    // ---- Push CTA partial into CTA0 + arrive; non-zero CTAs exit ----
    if (tid == 0) {
        float a = 0.f;
#pragma unroll
        for (int ww = 0; ww < 16; ++ww) a += red[ww];
        dsmem_st(&cpart[bid], 0, a);
        mbar_arrive_rank(&mbarC, 0);
    }
    if (bid != 0) return;

    // ---- CTA0: wait for 8 arrivals, finalize, write 8 outputs ----
    if (tid == 0) mbar_wait0(&mbarC);
    if (wid == 0) {
        __syncwarp();
        float cp = (lane < NC) ? cpart[lane] : 0.f;
        cp = warp_sum(cp);
        float ws = warp_sum(w_pre);
        if (lane < 8)
            out[lane] = cp * (1.f / 4096.f) * ws + b_pre;
    }
}

extern "C" void kernel_launch(void* const* d_in, const int* in_sizes, int n_in,
                              void* d_out, int out_size) {
    const float* x  = (const float*)d_in[0];   // (8,1,65,65)
    const float* w  = (const float*)d_in[1];   // (1,64)
    const float* pb = (const float*)d_in[2];   // (1,)
    float* out = (float*)d_out;                // (8,)

    k_fused<<<NC, 512>>>(x, w, pb, out);
}

// round 14
// speedup vs baseline: 1.2857x; 1.2857x over previous
#include <cuda_runtime.h>
#include <cstdint>

// ConvAttentionModule — one kernel, 8-CTA cluster. R8 sync skeleton (wall-best):
// ONE mid-kernel cluster barrier + ONE final mbarrier; pull-based gather.
//   s[n]   = tanh( (1/32) * Sum_{8 batches, 2x2 patch} x ),  n in [0,4096)
//   ctx[n] = g(t)/h(t), t = 8 s[n], h(t) = Sum_m exp(t s_m), g = h'
//            via degree-15 Taylor in moments M_k = Sum_m s_m^k  (gate 1e-3)
//   out[b] = (mean_n ctx[n]) * Sum_d w[d] + b0              (same for all b)
//
// R14 micro-fixes vs R8 (sync structure unchanged):
//  - gather parallelized: 128 threads, ONE remote pull each (vs 16x8 serial)
//  - final red[] combine via warp_sum in warp 0 (vs serial 16-add in tid0)
// No global scratch, no atomics -> replay-deterministic.

#define KM  16           // moments M_1..M_16 (series degree 15) = 16 warps
#define NC  8            // cluster size = grid size
#define NLD 585          // 9 rows x 65 cols per CTA

__constant__ float c_invk[KM] = {
    0.f,    1.f,    1.f/2,  1.f/3,  1.f/4,  1.f/5,  1.f/6,  1.f/7,
    1.f/8,  1.f/9,  1.f/10, 1.f/11, 1.f/12, 1.f/13, 1.f/14, 1.f/15
};

__device__ __forceinline__ float warp_sum(float v) {
    v += __shfl_xor_sync(0xffffffffu, v, 16);
    v += __shfl_xor_sync(0xffffffffu, v, 8);
    v += __shfl_xor_sync(0xffffffffu, v, 4);
    v += __shfl_xor_sync(0xffffffffu, v, 2);
    v += __shfl_xor_sync(0xffffffffu, v, 1);
    return v;
}

__device__ __forceinline__ uint32_t smem_u32(const void* p) {
    return (uint32_t)__cvta_generic_to_shared(p);
}
__device__ __forceinline__ float dsmem_ld(const float* p, uint32_t rank) {
    uint32_t a = smem_u32(p), ra; float v;
    asm volatile("mapa.shared::cluster.u32 %0, %1, %2;" : "=r"(ra) : "r"(a), "r"(rank));
    asm volatile("ld.shared::cluster.f32 %0, [%1];" : "=f"(v) : "r"(ra));
    return v;
}
__device__ __forceinline__ void dsmem_st(float* p, uint32_t rank, float v) {
    uint32_t a = smem_u32(p), ra;
    asm volatile("mapa.shared::cluster.u32 %0, %1, %2;" : "=r"(ra) : "r"(a), "r"(rank));
    asm volatile("st.shared::cluster.f32 [%0], %1;" :: "r"(ra), "f"(v) : "memory");
}
// release-arrive (cluster scope) on `rank`'s copy of this mbarrier
__device__ __forceinline__ void mbar_arrive_rank(void* mbar, uint32_t rank) {
    uint32_t a = smem_u32(mbar), ra;
    asm volatile("mapa.shared::cluster.u32 %0, %1, %2;" : "=r"(ra) : "r"(a), "r"(rank));
    asm volatile("mbarrier.arrive.release.cluster.shared::cluster.b64 _, [%0];"
                 :: "r"(ra) : "memory");
}
// acquire-wait (cluster scope) on the LOCAL mbarrier, phase parity 0
__device__ __forceinline__ void mbar_wait0(void* mbar) {
    uint32_t a = smem_u32(mbar);
    asm volatile(
        "{\n\t"
        ".reg .pred P;\n\t"
        "WAIT_%=:\n\t"
        "mbarrier.try_wait.parity.acquire.cluster.shared::cta.b64 P, [%0], 0, 0x989680;\n\t"
        "@P bra.uni DONE_%=;\n\t"
        "bra.uni WAIT_%=;\n\t"
        "DONE_%=:\n\t"
        "}" :: "r"(a) : "memory");
}
#define CLUSTER_SYNC() do { \
    asm volatile("barrier.cluster.arrive.aligned;" ::: "memory"); \
    asm volatile("barrier.cluster.wait.aligned;"   ::: "memory"); \
} while (0)

__global__ void __launch_bounds__(512, 1) __cluster_dims__(NC, 1, 1)
k_fused(const float* __restrict__ x, const float* __restrict__ w,
        const float* __restrict__ pb, float* __restrict__ out) {
    __shared__ float y[9 * 66];           // this CTA's 9 batch-summed rows
    __shared__ float spow[KM][512];       // s^{k+1} per thread (32 KB)
    __shared__ float Mpart[KM];           // this CTA's moment partials (pulled by peers)
    __shared__ float Mrecv[NC][KM];       // pulled peer partials
    __shared__ float Ms[KM + 1];          // finalized moments, Ms[0] = 4096
    __shared__ float red[16];             // per-warp ctx partials
    __shared__ float cpart[NC];           // per-CTA ctx partials (CTA0 target)
    __shared__ alignas(8) unsigned long long mbarC;  // 8 arrivals (CTA0 only)

    const int tid  = threadIdx.x;         // 512
    const int bid  = blockIdx.x;          // 8
    const int wid  = tid >> 5;            // 16 warps
    const int lane = tid & 31;

    // Prefetch final-stage operands (CTA0 warp0) + init mbarrier
    float w_pre = 0.f, b_pre = 0.f;
    if (bid == 0 && tid < 32) {
        w_pre = w[lane] + w[lane + 32];
        b_pre = pb[0];
    }
    if (tid == 0) {
        uint32_t aC = smem_u32(&mbarC);
        asm volatile("mbarrier.init.shared.b64 [%0], %1;" :: "r"(aC), "r"(NC) : "memory");
    }

    // ---- Loads first: 16 LDGs in flight immediately ----
    const float* xb = x + 520 * bid;      // rows 8*bid .. 8*bid+8
    const int i0 = tid, i1 = tid + 512;
    const bool v1 = (i1 < NLD);
    float r0[8], r1[8];
#pragma unroll
    for (int b = 0; b < 8; ++b) r0[b] = xb[b * 4225 + i0];
#pragma unroll
    for (int b = 0; b < 8; ++b) r1[b] = v1 ? xb[b * 4225 + i1] : 0.f;

    // ---- Phase A: consume loads, batch-summed rows into smem ----
    {
        float a0 = (r0[0] + r0[1]) + (r0[2] + r0[3])
                 + (r0[4] + r0[5]) + (r0[6] + r0[7]);
        int r = i0 / 65, c = i0 - r * 65;
        y[r * 66 + c] = a0;
        if (v1) {
            float a1 = (r1[0] + r1[1]) + (r1[2] + r1[3])
                     + (r1[4] + r1[5]) + (r1[6] + r1[7]);
            int r2 = i1 / 65, c2 = i1 - r2 * 65;
            y[r2 * 66 + c2] = a1;
        }
    }
    __syncthreads();

    // ---- Phase B: patch scalar + power table ----
    const int il = tid >> 6, j = tid & 63;
    const float* p = &y[il * 66 + j];
    const float s = tanhf((p[0] + p[1] + p[66] + p[67]) * 0.03125f);
    {
        float pw = s;
        spow[0][tid] = pw;
#pragma unroll
        for (int k = 1; k < KM; ++k) { pw *= s; spow[k][tid] = pw; }
    }
    __syncthreads();

    // ---- Phase C: warp w sums order w+1 (coalesced LDS, one warp_sum) ----
    {
        float a = 0.f;
#pragma unroll
        for (int i = 0; i < 16; ++i) a += spow[wid][i * 32 + lane];
        a = warp_sum(a);
        if (lane == 0) Mpart[wid] = a;
    }

    // ---- THE cluster barrier: publishes Mpart everywhere + mbarC init ----
    CLUSTER_SYNC();

    // ---- Parallel pull: 128 threads, one (rank, order) each ----
    if (tid < NC * KM) {
        int r = tid >> 4, k = tid & 15;
        Mrecv[r][k] = dsmem_ld(&Mpart[k], (uint32_t)r);
    }
    __syncthreads();
    if (tid < KM) {
        float m = 0.f;
#pragma unroll
        for (int r = 0; r < NC; ++r) m += Mrecv[r][tid];
        Ms[tid + 1] = m;
    }
    if (tid == KM) Ms[0] = 4096.f;
    __syncthreads();

    // ---- Phase D: degree-15 series + block reduction ----
    const float t = 8.f * s;
    float term = 1.f;
    float hh = Ms[0];
    float gg = Ms[1];
#pragma unroll
    for (int k = 1; k <= KM - 1; ++k) {
        term *= t * c_invk[k];            // t^k / k!
        hh += Ms[k]     * term;
        gg += Ms[k + 1] * term;
    }
    float v = warp_sum(__fdividef(gg, hh));
    if (lane == 0) red[wid] = v;
    __syncthreads();

    // ---- Warp 0: warp-sum the 16 partials, push to CTA0, arrive ----
    if (wid == 0) {
        float a = (lane < 16) ? red[lane] : 0.f;
        a = warp_sum(a);
        if (lane == 0) {
            dsmem_st(&cpart[bid], 0, a);
            mbar_arrive_rank(&mbarC, 0);
        }
    }
    if (bid != 0) return;

    // ---- CTA0: wait for 8 arrivals, finalize, write 8 outputs ----
    if (tid == 0) mbar_wait0(&mbarC);
    if (wid == 0) {
        __syncwarp();
        float cp = (lane < NC) ? cpart[lane] : 0.f;
        cp = warp_sum(cp);
        float ws = warp_sum(w_pre);
        if (lane < 8)
            out[lane] = cp * (1.f / 4096.f) * ws + b_pre;
    }
}

extern "C" void kernel_launch(void* const* d_in, const int* in_sizes, int n_in,
                              void* d_out, int out_size) {
    const float* x  = (const float*)d_in[0];   // (8,1,65,65)
    const float* w  = (const float*)d_in[1];   // (1,64)
    const float* pb = (const float*)d_in[2];   // (1,)
    float* out = (float*)d_out;                // (8,)

    k_fused<<<NC, 512>>>(x, w, pb, out);
}